// round 9
// baseline (speedup 1.0000x reference)
#include <cuda_runtime.h>

#define EPS 1e-5f
#define C_DIM 64
#define B_DIM 8
#define CTX_DIM 256

// Fused modulation coefficients: [0..511]   = A[b][c] = gamma[c]*(1+scale[b][c])
//                                [512..1023]= B[b][c] = beta[c]*(1+scale[b][c]) + shift[b][c]
__device__ __align__(16) float g_coef[2 * B_DIM * C_DIM];
// g_bound[k] = first row whose batch >= k+1. batch(row) = #{k : bound[k] <= row}
__device__ int g_bound[B_DIM - 1];

// ---------------------------------------------------------------------------
// Setup kernel: blocks 0..63 = tiny MLP (one warp per (batch,channel) pair);
// blocks 64..70 = one block per batch boundary, 257-way block-parallel search.
// ---------------------------------------------------------------------------
__global__ void __launch_bounds__(256)
setup_kernel(const float* __restrict__ token,  // [8,256]
             const float* __restrict__ W,      // [128,256]
             const float* __restrict__ bvec,   // [128]
             const float* __restrict__ gamma,  // [64]
             const float* __restrict__ beta,   // [64]
             const int* __restrict__ coors,    // [N,4] int32, col 0 sorted
             int n_rows)
{
    const int tid  = threadIdx.x;
    const int warp = tid >> 5;
    const int lane = tid & 31;

    if (blockIdx.x < 64) {
        const int wg = blockIdx.x * 8 + warp;   // 0..511
        const int j = wg >> 6;
        const int c = wg & 63;

        const float* trow = token + j * CTX_DIM;
        const float* wsh  = W + c * CTX_DIM;
        const float* wsc  = W + (C_DIM + c) * CTX_DIM;

        float tv[8], wa[8], wb[8];
#pragma unroll
        for (int i = 0; i < 8; ++i) {
            const int k = lane + 32 * i;
            tv[i] = __ldg(trow + k);
            wa[i] = __ldg(wsh + k);
            wb[i] = __ldg(wsc + k);
        }
        float acc_sh = 0.0f, acc_sc = 0.0f;
#pragma unroll
        for (int i = 0; i < 8; ++i) {
            const float s = tv[i] / (1.0f + expf(-tv[i]));
            acc_sh += s * wa[i];
            acc_sc += s * wb[i];
        }
#pragma unroll
        for (int o = 16; o >= 1; o >>= 1) {
            acc_sh += __shfl_xor_sync(0xffffffffu, acc_sh, o);
            acc_sc += __shfl_xor_sync(0xffffffffu, acc_sc, o);
        }
        if (lane == 0) {
            const float shift = acc_sh + bvec[c];
            const float scale = acc_sc + bvec[C_DIM + c];
            g_coef[j * C_DIM + c]                 = gamma[c] * (1.0f + scale);
            g_coef[B_DIM * C_DIM + j * C_DIM + c] = beta[c] * (1.0f + scale) + shift;
        }
    } else {
        __shared__ int s_lo, s_hi;
        const int k = (int)blockIdx.x - 63;      // 1..7
        if (tid == 0) { s_lo = 0; s_hi = n_rows; }
        __syncthreads();

        while (s_hi - s_lo > 256) {
            const int lo = s_lo, hi = s_hi;
            const long long len = hi - lo;
            const int pos = lo + (int)(((long long)(tid + 1) * len) / 257);
            const bool ge = __ldg(coors + (long long)pos * 4) >= k;
            const int posL = lo + (int)(((long long)tid * len) / 257);
            const bool geL = (tid == 0) ? false
                                        : (__ldg(coors + (long long)posL * 4) >= k);
            __syncthreads();
            if (ge && !geL) {
                s_lo = (tid == 0) ? lo : posL;
                s_hi = pos;
            }
            if (tid == 255 && !ge) s_lo = pos;
            __syncthreads();
        }
        __shared__ int s_ans;
        if (tid == 0) s_ans = s_hi;
        __syncthreads();
        const int lo = s_lo, hi = s_hi;
        const int pos = lo + tid;
        if (pos < hi && __ldg(coors + (long long)pos * 4) >= k) {
            atomicMin(&s_ans, pos);
        }
        __syncthreads();
        if (tid == 0) g_bound[k - 1] = s_ans;
    }
}

// ---------------------------------------------------------------------------
// Persistent norm kernel: one resident wave, each CTA grid-strides over
// 64-row tiles. Coefficients staged ONCE per CTA. 8 lanes per row, 2 float4
// per lane, 2 rows per thread per tile.
// ---------------------------------------------------------------------------
template <bool GUARD>
__global__ void __launch_bounds__(256, 6)
norm_mod_kernel(const float* __restrict__ x,
                float* __restrict__ out,
                int n_rows, int n_tiles)
{
    __shared__ float sA[B_DIM * C_DIM];
    __shared__ float sB[B_DIM * C_DIM];
    __shared__ int sbnd[B_DIM - 1];

    const int tid = threadIdx.x;
    for (int i = tid; i < B_DIM * C_DIM; i += 256) {
        sA[i] = g_coef[i];
        sB[i] = g_coef[B_DIM * C_DIM + i];
    }
    if (tid < B_DIM - 1) sbnd[tid] = g_bound[tid];
    __syncthreads();

    int bnd[B_DIM - 1];
#pragma unroll
    for (int k = 0; k < B_DIM - 1; ++k) bnd[k] = sbnd[k];

    const int warp = tid >> 5;
    const int lane = tid & 31;
    const int g    = lane >> 3;   // row slot 0..3 within warp
    const int sub  = lane & 7;    // lane within row

    const int tile_stride = gridDim.x;          // tiles advance by grid size
    const int row_off  = warp * 8 + g;          // 0..31 (rows0); rows1 = +4
    const long long elem_stride = (long long)tile_stride * 64 * 16;  // float4 units

    int rows0 = blockIdx.x * 64 + row_off;
    const float4* p0 = reinterpret_cast<const float4*>(x) + (long long)rows0 * 16 + sub;
    float4* q0 = reinterpret_cast<float4*>(out) + (long long)rows0 * 16 + sub;

    for (int t = blockIdx.x; t < n_tiles;
         t += tile_stride, rows0 += tile_stride * 64, p0 += elem_stride, q0 += elem_stride)
    {
        const int rows1 = rows0 + 4;
        const bool ok0 = !GUARD || rows0 < n_rows;
        const bool ok1 = !GUARD || rows1 < n_rows;

        const float4 z = make_float4(0.f, 0.f, 0.f, 0.f);
        const float4* p1 = p0 + 64;   // 4 rows * 16 float4
        float4 v00 = ok0 ? __ldcs(p0)     : z;
        float4 v01 = ok0 ? __ldcs(p0 + 8) : z;
        float4 v10 = ok1 ? __ldcs(p1)     : z;
        float4 v11 = ok1 ? __ldcs(p1 + 8) : z;

        float s0  = (v00.x + v00.y) + (v00.z + v00.w) + (v01.x + v01.y) + (v01.z + v01.w);
        float s20 = v00.x * v00.x + v00.y * v00.y + v00.z * v00.z + v00.w * v00.w
                  + v01.x * v01.x + v01.y * v01.y + v01.z * v01.z + v01.w * v01.w;
        float s1  = (v10.x + v10.y) + (v10.z + v10.w) + (v11.x + v11.y) + (v11.z + v11.w);
        float s21 = v10.x * v10.x + v10.y * v10.y + v10.z * v10.z + v10.w * v10.w
                  + v11.x * v11.x + v11.y * v11.y + v11.z * v11.z + v11.w * v11.w;

#pragma unroll
        for (int o = 4; o >= 1; o >>= 1) {
            s0  += __shfl_xor_sync(0xffffffffu, s0,  o);
            s20 += __shfl_xor_sync(0xffffffffu, s20, o);
            s1  += __shfl_xor_sync(0xffffffffu, s1,  o);
            s21 += __shfl_xor_sync(0xffffffffu, s21, o);
        }

        if (ok0) {
            const float mu  = s0 * (1.0f / 64.0f);
            const float var = s20 * (1.0f / 64.0f) - mu * mu;
            const float rs  = rsqrtf(var + EPS);
            int b = 0;
#pragma unroll
            for (int k = 0; k < B_DIM - 1; ++k) b += (rows0 >= bnd[k]);
            const float4* ap = reinterpret_cast<const float4*>(sA + b * C_DIM);
            const float4* bp = reinterpret_cast<const float4*>(sB + b * C_DIM);
            const float4 a0 = ap[sub], a1 = ap[sub + 8];
            const float4 b0 = bp[sub], b1 = bp[sub + 8];
            float4 o0, o1;
            o0.x = (v00.x - mu) * rs * a0.x + b0.x;
            o0.y = (v00.y - mu) * rs * a0.y + b0.y;
            o0.z = (v00.z - mu) * rs * a0.z + b0.z;
            o0.w = (v00.w - mu) * rs * a0.w + b0.w;
            o1.x = (v01.x - mu) * rs * a1.x + b1.x;
            o1.y = (v01.y - mu) * rs * a1.y + b1.y;
            o1.z = (v01.z - mu) * rs * a1.z + b1.z;
            o1.w = (v01.w - mu) * rs * a1.w + b1.w;
            __stcs(q0, o0);
            __stcs(q0 + 8, o1);
        }
        if (ok1) {
            const float mu  = s1 * (1.0f / 64.0f);
            const float var = s21 * (1.0f / 64.0f) - mu * mu;
            const float rs  = rsqrtf(var + EPS);
            int b = 0;
#pragma unroll
            for (int k = 0; k < B_DIM - 1; ++k) b += (rows1 >= bnd[k]);
            const float4* ap = reinterpret_cast<const float4*>(sA + b * C_DIM);
            const float4* bp = reinterpret_cast<const float4*>(sB + b * C_DIM);
            const float4 a0 = ap[sub], a1 = ap[sub + 8];
            const float4 b0 = bp[sub], b1 = bp[sub + 8];
            float4* q1 = q0 + 64;
            float4 o0, o1;
            o0.x = (v10.x - mu) * rs * a0.x + b0.x;
            o0.y = (v10.y - mu) * rs * a0.y + b0.y;
            o0.z = (v10.z - mu) * rs * a0.z + b0.z;
            o0.w = (v10.w - mu) * rs * a0.w + b0.w;
            o1.x = (v11.x - mu) * rs * a1.x + b1.x;
            o1.y = (v11.y - mu) * rs * a1.y + b1.y;
            o1.z = (v11.z - mu) * rs * a1.z + b1.z;
            o1.w = (v11.w - mu) * rs * a1.w + b1.w;
            __stcs(q1, o0);
            __stcs(q1 + 8, o1);
        }
    }
}

// ---------------------------------------------------------------------------
// Launch. Inputs (metadata order): x, dataset_token, gamma, beta, W, b, coors
// ---------------------------------------------------------------------------
extern "C" void kernel_launch(void* const* d_in, const int* in_sizes, int n_in,
                              void* d_out, int out_size)
{
    const float* x      = (const float*)d_in[0];
    const float* token  = (const float*)d_in[1];
    const float* gamma  = (const float*)d_in[2];
    const float* beta   = (const float*)d_in[3];
    const float* W      = (const float*)d_in[4];
    const float* bvec   = (const float*)d_in[5];
    const int*   coors  = (const int*)d_in[6];
    float* out = (float*)d_out;

    const int n_rows = in_sizes[0] / C_DIM;
    const int n_tiles = (n_rows + 63) / 64;

    setup_kernel<<<64 + (B_DIM - 1), 256>>>(token, W, bvec, gamma, beta, coors, n_rows);

    int sms = 148;
    cudaDeviceGetAttribute(&sms, cudaDevAttrMultiProcessorCount, 0);
    int grid = sms * 6;
    if (grid > n_tiles) grid = n_tiles;

    if (n_rows % 64 == 0) {
        norm_mod_kernel<false><<<grid, 256>>>(x, out, n_rows, n_tiles);
    } else {
        norm_mod_kernel<true><<<grid, 256>>>(x, out, n_rows, n_tiles);
    }
}

// round 10
// speedup vs baseline: 1.1632x; 1.1632x over previous
#include <cuda_runtime.h>

#define EPS 1e-5f
#define C_DIM 64
#define B_DIM 8
#define CTX_DIM 256

// Fused modulation coefficients: [0..511]   = A[b][c] = gamma[c]*(1+scale[b][c])
//                                [512..1023]= B[b][c] = beta[c]*(1+scale[b][c]) + shift[b][c]
__device__ __align__(16) float g_coef[2 * B_DIM * C_DIM];
// g_bound[k] = first row whose batch >= k+1. batch(row) = #{k : bound[k] <= row}
__device__ int g_bound[B_DIM - 1];

// ---------------------------------------------------------------------------
// Setup kernel: blocks 0..63 = tiny MLP (one warp per (batch,channel) pair);
// blocks 64..70 = one block per batch boundary, 257-way block-parallel search.
// Triggers programmatic launch completion immediately so the norm kernel can
// start loading x while this runs.
// ---------------------------------------------------------------------------
__global__ void __launch_bounds__(256)
setup_kernel(const float* __restrict__ token,  // [8,256]
             const float* __restrict__ W,      // [128,256]
             const float* __restrict__ bvec,   // [128]
             const float* __restrict__ gamma,  // [64]
             const float* __restrict__ beta,   // [64]
             const int* __restrict__ coors,    // [N,4] int32, col 0 sorted
             int n_rows)
{
    cudaTriggerProgrammaticLaunchCompletion();

    const int tid  = threadIdx.x;
    const int warp = tid >> 5;
    const int lane = tid & 31;

    if (blockIdx.x < 64) {
        const int wg = blockIdx.x * 8 + warp;   // 0..511
        const int j = wg >> 6;
        const int c = wg & 63;

        const float* trow = token + j * CTX_DIM;
        const float* wsh  = W + c * CTX_DIM;
        const float* wsc  = W + (C_DIM + c) * CTX_DIM;

        float tv[8], wa[8], wb[8];
#pragma unroll
        for (int i = 0; i < 8; ++i) {
            const int k = lane + 32 * i;
            tv[i] = __ldg(trow + k);
            wa[i] = __ldg(wsh + k);
            wb[i] = __ldg(wsc + k);
        }
        float acc_sh = 0.0f, acc_sc = 0.0f;
#pragma unroll
        for (int i = 0; i < 8; ++i) {
            const float s = tv[i] / (1.0f + expf(-tv[i]));
            acc_sh += s * wa[i];
            acc_sc += s * wb[i];
        }
#pragma unroll
        for (int o = 16; o >= 1; o >>= 1) {
            acc_sh += __shfl_xor_sync(0xffffffffu, acc_sh, o);
            acc_sc += __shfl_xor_sync(0xffffffffu, acc_sc, o);
        }
        if (lane == 0) {
            const float shift = acc_sh + bvec[c];
            const float scale = acc_sc + bvec[C_DIM + c];
            g_coef[j * C_DIM + c]                 = gamma[c] * (1.0f + scale);
            g_coef[B_DIM * C_DIM + j * C_DIM + c] = beta[c] * (1.0f + scale) + shift;
        }
    } else {
        __shared__ int s_lo, s_hi;
        const int k = (int)blockIdx.x - 63;      // 1..7
        if (tid == 0) { s_lo = 0; s_hi = n_rows; }
        __syncthreads();

        while (s_hi - s_lo > 256) {
            const int lo = s_lo, hi = s_hi;
            const long long len = hi - lo;
            const int pos = lo + (int)(((long long)(tid + 1) * len) / 257);
            const bool ge = __ldg(coors + (long long)pos * 4) >= k;
            const int posL = lo + (int)(((long long)tid * len) / 257);
            const bool geL = (tid == 0) ? false
                                        : (__ldg(coors + (long long)posL * 4) >= k);
            __syncthreads();
            if (ge && !geL) {
                s_lo = (tid == 0) ? lo : posL;
                s_hi = pos;
            }
            if (tid == 255 && !ge) s_lo = pos;
            __syncthreads();
        }
        __shared__ int s_ans;
        if (tid == 0) s_ans = s_hi;
        __syncthreads();
        const int lo = s_lo, hi = s_hi;
        const int pos = lo + tid;
        if (pos < hi && __ldg(coors + (long long)pos * 4) >= k) {
            atomicMin(&s_ans, pos);
        }
        __syncthreads();
        if (tid == 0) g_bound[k - 1] = s_ans;
    }
}

// ---------------------------------------------------------------------------
// Norm kernel (R5 shape — best measured): 8 lanes per row, 2 float4 per lane,
// 2 rows per thread; block covers 64 rows. PDL: loads + reduction issue BEFORE
// cudaGridDependencySynchronize(), hiding setup latency.
// ---------------------------------------------------------------------------
template <bool GUARD>
__global__ void __launch_bounds__(256)
norm_mod_kernel(const float* __restrict__ x,
                float* __restrict__ out,
                int n_rows)
{
    __shared__ float sA[B_DIM * C_DIM];
    __shared__ float sB[B_DIM * C_DIM];
    __shared__ int sbnd[B_DIM - 1];

    const int tid  = threadIdx.x;
    const int warp = tid >> 5;
    const int lane = tid & 31;
    const int g    = lane >> 3;   // row slot 0..3 within warp
    const int sub  = lane & 7;    // lane within row

    const int base  = blockIdx.x * 64 + warp * 8 + g;
    const int rows0 = base;
    const int rows1 = base + 4;
    const bool ok0 = !GUARD || rows0 < n_rows;
    const bool ok1 = !GUARD || rows1 < n_rows;

    // Phase 1: stream loads + reduction (independent of setup results).
    const float4 z = make_float4(0.f, 0.f, 0.f, 0.f);
    const float4* p0 = reinterpret_cast<const float4*>(x) + (long long)rows0 * 16;
    const float4* p1 = reinterpret_cast<const float4*>(x) + (long long)rows1 * 16;
    float4 v00 = ok0 ? __ldcs(p0 + sub)     : z;
    float4 v01 = ok0 ? __ldcs(p0 + sub + 8) : z;
    float4 v10 = ok1 ? __ldcs(p1 + sub)     : z;
    float4 v11 = ok1 ? __ldcs(p1 + sub + 8) : z;

    float s0  = (v00.x + v00.y) + (v00.z + v00.w) + (v01.x + v01.y) + (v01.z + v01.w);
    float s20 = v00.x * v00.x + v00.y * v00.y + v00.z * v00.z + v00.w * v00.w
              + v01.x * v01.x + v01.y * v01.y + v01.z * v01.z + v01.w * v01.w;
    float s1  = (v10.x + v10.y) + (v10.z + v10.w) + (v11.x + v11.y) + (v11.z + v11.w);
    float s21 = v10.x * v10.x + v10.y * v10.y + v10.z * v10.z + v10.w * v10.w
              + v11.x * v11.x + v11.y * v11.y + v11.z * v11.z + v11.w * v11.w;

#pragma unroll
    for (int o = 4; o >= 1; o >>= 1) {
        s0  += __shfl_xor_sync(0xffffffffu, s0,  o);
        s20 += __shfl_xor_sync(0xffffffffu, s20, o);
        s1  += __shfl_xor_sync(0xffffffffu, s1,  o);
        s21 += __shfl_xor_sync(0xffffffffu, s21, o);
    }

    // Phase 2: wait for setup kernel's writes, then stage coefficients.
    cudaGridDependencySynchronize();

    for (int i = tid; i < B_DIM * C_DIM; i += 256) {
        sA[i] = g_coef[i];
        sB[i] = g_coef[B_DIM * C_DIM + i];
    }
    if (tid < B_DIM - 1) sbnd[tid] = g_bound[tid];
    __syncthreads();

    int bnd[B_DIM - 1];
#pragma unroll
    for (int k = 0; k < B_DIM - 1; ++k) bnd[k] = sbnd[k];

    if (ok0) {
        const float mu  = s0 * (1.0f / 64.0f);
        const float var = s20 * (1.0f / 64.0f) - mu * mu;
        const float rs  = rsqrtf(var + EPS);
        int b = 0;
#pragma unroll
        for (int k = 0; k < B_DIM - 1; ++k) b += (rows0 >= bnd[k]);
        const float4* ap = reinterpret_cast<const float4*>(sA + b * C_DIM);
        const float4* bp = reinterpret_cast<const float4*>(sB + b * C_DIM);
        const float4 a0 = ap[sub], a1 = ap[sub + 8];
        const float4 b0 = bp[sub], b1 = bp[sub + 8];
        float4* po = reinterpret_cast<float4*>(out) + (long long)rows0 * 16;
        float4 o0, o1;
        o0.x = (v00.x - mu) * rs * a0.x + b0.x;
        o0.y = (v00.y - mu) * rs * a0.y + b0.y;
        o0.z = (v00.z - mu) * rs * a0.z + b0.z;
        o0.w = (v00.w - mu) * rs * a0.w + b0.w;
        o1.x = (v01.x - mu) * rs * a1.x + b1.x;
        o1.y = (v01.y - mu) * rs * a1.y + b1.y;
        o1.z = (v01.z - mu) * rs * a1.z + b1.z;
        o1.w = (v01.w - mu) * rs * a1.w + b1.w;
        __stcs(po + sub, o0);
        __stcs(po + sub + 8, o1);
    }
    if (ok1) {
        const float mu  = s1 * (1.0f / 64.0f);
        const float var = s21 * (1.0f / 64.0f) - mu * mu;
        const float rs  = rsqrtf(var + EPS);
        int b = 0;
#pragma unroll
        for (int k = 0; k < B_DIM - 1; ++k) b += (rows1 >= bnd[k]);
        const float4* ap = reinterpret_cast<const float4*>(sA + b * C_DIM);
        const float4* bp = reinterpret_cast<const float4*>(sB + b * C_DIM);
        const float4 a0 = ap[sub], a1 = ap[sub + 8];
        const float4 b0 = bp[sub], b1 = bp[sub + 8];
        float4* po = reinterpret_cast<float4*>(out) + (long long)rows1 * 16;
        float4 o0, o1;
        o0.x = (v10.x - mu) * rs * a0.x + b0.x;
        o0.y = (v10.y - mu) * rs * a0.y + b0.y;
        o0.z = (v10.z - mu) * rs * a0.z + b0.z;
        o0.w = (v10.w - mu) * rs * a0.w + b0.w;
        o1.x = (v11.x - mu) * rs * a1.x + b1.x;
        o1.y = (v11.y - mu) * rs * a1.y + b1.y;
        o1.z = (v11.z - mu) * rs * a1.z + b1.z;
        o1.w = (v11.w - mu) * rs * a1.w + b1.w;
        __stcs(po + sub, o0);
        __stcs(po + sub + 8, o1);
    }
}

// ---------------------------------------------------------------------------
// Launch. Inputs (metadata order): x, dataset_token, gamma, beta, W, b, coors
// Norm kernel launched with Programmatic Stream Serialization (PDL) so it
// overlaps the setup kernel.
// ---------------------------------------------------------------------------
extern "C" void kernel_launch(void* const* d_in, const int* in_sizes, int n_in,
                              void* d_out, int out_size)
{
    const float* x      = (const float*)d_in[0];
    const float* token  = (const float*)d_in[1];
    const float* gamma  = (const float*)d_in[2];
    const float* beta   = (const float*)d_in[3];
    const float* W      = (const float*)d_in[4];
    const float* bvec   = (const float*)d_in[5];
    const int*   coors  = (const int*)d_in[6];
    float* out = (float*)d_out;

    const int n_rows = in_sizes[0] / C_DIM;
    const int grid = (n_rows + 63) / 64;

    setup_kernel<<<64 + (B_DIM - 1), 256>>>(token, W, bvec, gamma, beta, coors, n_rows);

    cudaLaunchConfig_t cfg = {};
    cfg.gridDim = dim3((unsigned)grid, 1, 1);
    cfg.blockDim = dim3(256, 1, 1);
    cfg.dynamicSmemBytes = 0;
    cfg.stream = 0;
    cudaLaunchAttribute attrs[1];
    attrs[0].id = cudaLaunchAttributeProgrammaticStreamSerialization;
    attrs[0].val.programmaticStreamSerializationAllowed = 1;
    cfg.attrs = attrs;
    cfg.numAttrs = 1;

    if (n_rows % 64 == 0) {
        cudaLaunchKernelEx(&cfg, norm_mod_kernel<false>, x, out, n_rows);
    } else {
        cudaLaunchKernelEx(&cfg, norm_mod_kernel<true>, x, out, n_rows);
    }
}

// round 11
// speedup vs baseline: 1.1660x; 1.0024x over previous
#include <cuda_runtime.h>

#define EPS 1e-5f
#define C_DIM 64
#define B_DIM 8
#define CTX_DIM 256

// Fused modulation coefficients: [0..511]   = A[b][c] = gamma[c]*(1+scale[b][c])
//                                [512..1023]= B[b][c] = beta[c]*(1+scale[b][c]) + shift[b][c]
__device__ __align__(16) float g_coef[2 * B_DIM * C_DIM];
// g_bound[k] = first row whose batch >= k+1. batch(row) = #{k : bound[k] <= row}
__device__ int g_bound[B_DIM - 1];

// ---------------------------------------------------------------------------
// Setup kernel: blocks 0..63 = tiny MLP (one warp per (batch,channel) pair);
// blocks 64..70 = one block per batch boundary, 257-way block-parallel search.
// Triggers programmatic launch completion at start so the norm kernel's CTAs
// are resident (and waiting cheaply) while this runs.
// ---------------------------------------------------------------------------
__global__ void __launch_bounds__(256)
setup_kernel(const float* __restrict__ token,  // [8,256]
             const float* __restrict__ W,      // [128,256]
             const float* __restrict__ bvec,   // [128]
             const float* __restrict__ gamma,  // [64]
             const float* __restrict__ beta,   // [64]
             const int* __restrict__ coors,    // [N,4] int32, col 0 sorted
             int n_rows)
{
    cudaTriggerProgrammaticLaunchCompletion();

    const int tid  = threadIdx.x;
    const int warp = tid >> 5;
    const int lane = tid & 31;

    if (blockIdx.x < 64) {
        const int wg = blockIdx.x * 8 + warp;   // 0..511
        const int j = wg >> 6;
        const int c = wg & 63;

        const float* trow = token + j * CTX_DIM;
        const float* wsh  = W + c * CTX_DIM;
        const float* wsc  = W + (C_DIM + c) * CTX_DIM;

        float tv[8], wa[8], wb[8];
#pragma unroll
        for (int i = 0; i < 8; ++i) {
            const int k = lane + 32 * i;
            tv[i] = __ldg(trow + k);
            wa[i] = __ldg(wsh + k);
            wb[i] = __ldg(wsc + k);
        }
        float acc_sh = 0.0f, acc_sc = 0.0f;
#pragma unroll
        for (int i = 0; i < 8; ++i) {
            const float s = tv[i] / (1.0f + expf(-tv[i]));
            acc_sh += s * wa[i];
            acc_sc += s * wb[i];
        }
#pragma unroll
        for (int o = 16; o >= 1; o >>= 1) {
            acc_sh += __shfl_xor_sync(0xffffffffu, acc_sh, o);
            acc_sc += __shfl_xor_sync(0xffffffffu, acc_sc, o);
        }
        if (lane == 0) {
            const float shift = acc_sh + bvec[c];
            const float scale = acc_sc + bvec[C_DIM + c];
            g_coef[j * C_DIM + c]                 = gamma[c] * (1.0f + scale);
            g_coef[B_DIM * C_DIM + j * C_DIM + c] = beta[c] * (1.0f + scale) + shift;
        }
    } else {
        __shared__ int s_lo, s_hi;
        const int k = (int)blockIdx.x - 63;      // 1..7
        if (tid == 0) { s_lo = 0; s_hi = n_rows; }
        __syncthreads();

        while (s_hi - s_lo > 256) {
            const int lo = s_lo, hi = s_hi;
            const long long len = hi - lo;
            const int pos = lo + (int)(((long long)(tid + 1) * len) / 257);
            const bool ge = __ldg(coors + (long long)pos * 4) >= k;
            const int posL = lo + (int)(((long long)tid * len) / 257);
            const bool geL = (tid == 0) ? false
                                        : (__ldg(coors + (long long)posL * 4) >= k);
            __syncthreads();
            if (ge && !geL) {
                s_lo = (tid == 0) ? lo : posL;
                s_hi = pos;
            }
            if (tid == 255 && !ge) s_lo = pos;
            __syncthreads();
        }
        __shared__ int s_ans;
        if (tid == 0) s_ans = s_hi;
        __syncthreads();
        const int lo = s_lo, hi = s_hi;
        const int pos = lo + tid;
        if (pos < hi && __ldg(coors + (long long)pos * 4) >= k) {
            atomicMin(&s_ans, pos);
        }
        __syncthreads();
        if (tid == 0) g_bound[k - 1] = s_ans;
    }
}

// ---------------------------------------------------------------------------
// Norm kernel — R5 body (best measured: 73.5us, DRAM 78.3%) with the PDL
// dependency wait at the TOP, so the streaming body is one uninterrupted flow.
// 8 lanes per row, 2 float4 per lane, 2 rows per thread; block covers 64 rows.
// ---------------------------------------------------------------------------
template <bool GUARD>
__global__ void __launch_bounds__(256)
norm_mod_kernel(const float* __restrict__ x,
                float* __restrict__ out,
                int n_rows)
{
    __shared__ float sA[B_DIM * C_DIM];
    __shared__ float sB[B_DIM * C_DIM];
    __shared__ int sbnd[B_DIM - 1];

    cudaGridDependencySynchronize();

    const int tid = threadIdx.x;
    for (int i = tid; i < B_DIM * C_DIM; i += 256) {
        sA[i] = g_coef[i];
        sB[i] = g_coef[B_DIM * C_DIM + i];
    }
    if (tid < B_DIM - 1) sbnd[tid] = g_bound[tid];
    __syncthreads();

    int bnd[B_DIM - 1];
#pragma unroll
    for (int k = 0; k < B_DIM - 1; ++k) bnd[k] = sbnd[k];

    const int warp = tid >> 5;
    const int lane = tid & 31;
    const int g    = lane >> 3;   // row slot 0..3 within warp
    const int sub  = lane & 7;    // lane within row

    const int base  = blockIdx.x * 64 + warp * 8 + g;
    const int rows0 = base;
    const int rows1 = base + 4;
    const bool ok0 = !GUARD || rows0 < n_rows;
    const bool ok1 = !GUARD || rows1 < n_rows;

    const float4 z = make_float4(0.f, 0.f, 0.f, 0.f);
    const float4* p0 = reinterpret_cast<const float4*>(x) + (long long)rows0 * 16;
    const float4* p1 = reinterpret_cast<const float4*>(x) + (long long)rows1 * 16;
    float4 v00 = ok0 ? __ldcs(p0 + sub)     : z;
    float4 v01 = ok0 ? __ldcs(p0 + sub + 8) : z;
    float4 v10 = ok1 ? __ldcs(p1 + sub)     : z;
    float4 v11 = ok1 ? __ldcs(p1 + sub + 8) : z;

    float s0  = (v00.x + v00.y) + (v00.z + v00.w) + (v01.x + v01.y) + (v01.z + v01.w);
    float s20 = v00.x * v00.x + v00.y * v00.y + v00.z * v00.z + v00.w * v00.w
              + v01.x * v01.x + v01.y * v01.y + v01.z * v01.z + v01.w * v01.w;
    float s1  = (v10.x + v10.y) + (v10.z + v10.w) + (v11.x + v11.y) + (v11.z + v11.w);
    float s21 = v10.x * v10.x + v10.y * v10.y + v10.z * v10.z + v10.w * v10.w
              + v11.x * v11.x + v11.y * v11.y + v11.z * v11.z + v11.w * v11.w;

#pragma unroll
    for (int o = 4; o >= 1; o >>= 1) {
        s0  += __shfl_xor_sync(0xffffffffu, s0,  o);
        s20 += __shfl_xor_sync(0xffffffffu, s20, o);
        s1  += __shfl_xor_sync(0xffffffffu, s1,  o);
        s21 += __shfl_xor_sync(0xffffffffu, s21, o);
    }

    if (ok0) {
        const float mu  = s0 * (1.0f / 64.0f);
        const float var = s20 * (1.0f / 64.0f) - mu * mu;
        const float rs  = rsqrtf(var + EPS);
        int b = 0;
#pragma unroll
        for (int k = 0; k < B_DIM - 1; ++k) b += (rows0 >= bnd[k]);
        const float4* ap = reinterpret_cast<const float4*>(sA + b * C_DIM);
        const float4* bp = reinterpret_cast<const float4*>(sB + b * C_DIM);
        const float4 a0 = ap[sub], a1 = ap[sub + 8];
        const float4 b0 = bp[sub], b1 = bp[sub + 8];
        float4* po = reinterpret_cast<float4*>(out) + (long long)rows0 * 16;
        float4 o0, o1;
        o0.x = (v00.x - mu) * rs * a0.x + b0.x;
        o0.y = (v00.y - mu) * rs * a0.y + b0.y;
        o0.z = (v00.z - mu) * rs * a0.z + b0.z;
        o0.w = (v00.w - mu) * rs * a0.w + b0.w;
        o1.x = (v01.x - mu) * rs * a1.x + b1.x;
        o1.y = (v01.y - mu) * rs * a1.y + b1.y;
        o1.z = (v01.z - mu) * rs * a1.z + b1.z;
        o1.w = (v01.w - mu) * rs * a1.w + b1.w;
        __stcs(po + sub, o0);
        __stcs(po + sub + 8, o1);
    }
    if (ok1) {
        const float mu  = s1 * (1.0f / 64.0f);
        const float var = s21 * (1.0f / 64.0f) - mu * mu;
        const float rs  = rsqrtf(var + EPS);
        int b = 0;
#pragma unroll
        for (int k = 0; k < B_DIM - 1; ++k) b += (rows1 >= bnd[k]);
        const float4* ap = reinterpret_cast<const float4*>(sA + b * C_DIM);
        const float4* bp = reinterpret_cast<const float4*>(sB + b * C_DIM);
        const float4 a0 = ap[sub], a1 = ap[sub + 8];
        const float4 b0 = bp[sub], b1 = bp[sub + 8];
        float4* po = reinterpret_cast<float4*>(out) + (long long)rows1 * 16;
        float4 o0, o1;
        o0.x = (v10.x - mu) * rs * a0.x + b0.x;
        o0.y = (v10.y - mu) * rs * a0.y + b0.y;
        o0.z = (v10.z - mu) * rs * a0.z + b0.z;
        o0.w = (v10.w - mu) * rs * a0.w + b0.w;
        o1.x = (v11.x - mu) * rs * a1.x + b1.x;
        o1.y = (v11.y - mu) * rs * a1.y + b1.y;
        o1.z = (v11.z - mu) * rs * a1.z + b1.z;
        o1.w = (v11.w - mu) * rs * a1.w + b1.w;
        __stcs(po + sub, o0);
        __stcs(po + sub + 8, o1);
    }
}

// ---------------------------------------------------------------------------
// Launch. Inputs (metadata order): x, dataset_token, gamma, beta, W, b, coors
// Norm kernel launched with Programmatic Stream Serialization (PDL).
// ---------------------------------------------------------------------------
extern "C" void kernel_launch(void* const* d_in, const int* in_sizes, int n_in,
                              void* d_out, int out_size)
{
    const float* x      = (const float*)d_in[0];
    const float* token  = (const float*)d_in[1];
    const float* gamma  = (const float*)d_in[2];
    const float* beta   = (const float*)d_in[3];
    const float* W      = (const float*)d_in[4];
    const float* bvec   = (const float*)d_in[5];
    const int*   coors  = (const int*)d_in[6];
    float* out = (float*)d_out;

    const int n_rows = in_sizes[0] / C_DIM;
    const int grid = (n_rows + 63) / 64;

    setup_kernel<<<64 + (B_DIM - 1), 256>>>(token, W, bvec, gamma, beta, coors, n_rows);

    cudaLaunchConfig_t cfg = {};
    cfg.gridDim = dim3((unsigned)grid, 1, 1);
    cfg.blockDim = dim3(256, 1, 1);
    cfg.dynamicSmemBytes = 0;
    cfg.stream = 0;
    cudaLaunchAttribute attrs[1];
    attrs[0].id = cudaLaunchAttributeProgrammaticStreamSerialization;
    attrs[0].val.programmaticStreamSerializationAllowed = 1;
    cfg.attrs = attrs;
    cfg.numAttrs = 1;

    if (n_rows % 64 == 0) {
        cudaLaunchKernelEx(&cfg, norm_mod_kernel<false>, x, out, n_rows);
    } else {
        cudaLaunchKernelEx(&cfg, norm_mod_kernel<true>, x, out, n_rows);
    }
}